// round 7
// baseline (speedup 1.0000x reference)
#include <cuda_runtime.h>
#include <math.h>
#include <math_constants.h>

#define BATCH 64
#define DIM   768
#define HW    3136          // 56*56
#define FREQ  256
#define NE    16
#define TOPK  4
#define NBLOCKS ((BATCH * DIM) / 8)   // 6144 blocks of 256 threads (8 warps)

// scratch (device globals: zero-initialized; tail block restores zeros each run)
__device__ float g_logits_main[BATCH * NE];   // atomic-accumulated pooled @ gate_w.T
__device__ float g_logits_freq[BATCH * NE];   // freq_emb @ freq_gate_w.T (plain writes)
__device__ unsigned int g_counter;            // last-block-done counter

// ---------------------------------------------------------------------------
// Single fused kernel. Streaming phase identical to the 87%-DRAM R2 kernel.
// Last-block election: __syncthreads() then gpu-scope fence + ticket in
// tid==0 ONLY (6144 fences total, not 1.57M — the R3/R4 regression source).
// Tail block runs the R6-simplified epilogue inline: no launch overhead,
// no grid-completion visibility wait.
// Output (float32): gates[64*16] | top_k_indices[64*4] | top_k_values[64*4] | aux_loss
// ---------------------------------------------------------------------------
__global__ void __launch_bounds__(256, 8) routing_fused_kernel(
    const float* __restrict__ x,
    const float* __restrict__ gate_w,
    const float* __restrict__ freq_emb,
    const float* __restrict__ fgate_w,
    const float* __restrict__ noise,
    const float* __restrict__ complexity,
    float* __restrict__ out) {

    const int tid = threadIdx.x;
    const int warp_id = (blockIdx.x * blockDim.x + tid) >> 5;
    const int lane = tid & 31;
    const int b = warp_id / DIM;
    const int d = warp_id - b * DIM;

    // ---- phase 1: stream one (b,d) row of x, reduce, scatter to logits ----
    const float4* row = reinterpret_cast<const float4*>(x + (size_t)warp_id * HW);
    float s = 0.0f;
#pragma unroll
    for (int t = 0; t < 3; ++t) {           // 784 float4: 3 x (8 x 32 lanes) + 16
        float4 v[8];
#pragma unroll
        for (int k = 0; k < 8; ++k)
            v[k] = __ldcs(&row[lane + 32 * (t * 8 + k)]);
#pragma unroll
        for (int k = 0; k < 8; ++k)
            s += (v[k].x + v[k].y) + (v[k].z + v[k].w);
    }
    if (lane < 16) {
        float4 v = __ldcs(&row[768 + lane]);
        s += (v.x + v.y) + (v.z + v.w);
    }
#pragma unroll
    for (int m = 16; m; m >>= 1) s += __shfl_xor_sync(0xffffffffu, s, m);

    const float pooled = s * (1.0f / (float)HW);
    if (lane < NE)
        atomicAdd(&g_logits_main[b * NE + lane], pooled * gate_w[lane * DIM + d]);

    if (d < NE) {                            // freq-emb logits ride along
        const int e = d;
        const float4* fr  = reinterpret_cast<const float4*>(freq_emb + b * FREQ);
        const float4* fgr = reinterpret_cast<const float4*>(fgate_w  + e * FREQ);
        float f = 0.0f;
#pragma unroll
        for (int j = 0; j < 2; ++j) {        // 64 float4 / 32 lanes
            float4 a = fr[lane + 32 * j];
            float4 w = fgr[lane + 32 * j];
            f += a.x * w.x + a.y * w.y + a.z * w.z + a.w * w.w;
        }
#pragma unroll
        for (int m = 16; m; m >>= 1) f += __shfl_xor_sync(0xffffffffu, f, m);
        if (lane == 0) g_logits_freq[b * NE + e] = f;
    }

    // ---- last-block election: fence + ticket in ONE thread per block ----
    __shared__ unsigned int s_last;
    __syncthreads();                         // block-scope: all warps' writes ordered
    if (tid == 0) {
        __threadfence();                     // gpu-scope release (1 thread only)
        unsigned int v = atomicAdd(&g_counter, 1u);
        s_last = (v == (unsigned int)(NBLOCKS - 1)) ? 1u : 0u;
    }
    __syncthreads();
    if (!s_last) return;

    // ---- phase 2 (tail block only): softmax / top-k / gates / aux loss ----
    __threadfence();                         // acquire side (one block, trivial)
    __shared__ float s_clean[BATCH * NE];
    __shared__ float s_p[BATCH * NE];

    const int e    = tid & 15;
    const int half = lane & 16;              // base lane of my 16-lane group
    const float noise_std = 1.0f / (float)NE;

#pragma unroll 1
    for (int iter = 0; iter < 4; ++iter) {   // 256 threads x 4 = 1024 (b,e)
        const int bb = iter * 16 + (tid >> 4);
        const int idx = bb * NE + e;
        const float logit = g_logits_main[idx] + g_logits_freq[idx];
        g_logits_main[idx] = 0.0f;           // restore for next replay
        const float noisy = logit + noise[idx] * noise_std;

        // softmaxes without max-subtraction (logits O(10); ratio identical)
        float ce  = __expf(logit);
        float ne_ = __expf(noisy);
        float cs = ce, ns = ne_;
#pragma unroll
        for (int m = 8; m; m >>= 1) {
            cs += __shfl_xor_sync(0xffffffffu, cs, m);
            ns += __shfl_xor_sync(0xffffffffu, ns, m);
        }
        const float clean = ce / cs;
        const float score = ne_ / ns;

        // rank of my noisy logit within the row (ties: lower index wins)
        int rank = 0;
#pragma unroll
        for (int j = 0; j < 16; ++j) {
            float vj = __shfl_sync(0xffffffffu, noisy, half + j);
            rank += (vj > noisy) || (vj == noisy && j < e);
        }

        // threshold = k-th largest noisy logit
        float thr = (rank == TOPK - 1) ? noisy : -CUDART_INF_F;
#pragma unroll
        for (int m = 8; m; m >>= 1) thr = fmaxf(thr, __shfl_xor_sync(0xffffffffu, thr, m));

        out[idx] = (rank < TOPK) ? score : 0.0f;
        if (rank < TOPK) {
            out[BATCH * NE + bb * TOPK + rank]                = (float)e;  // indices
            out[BATCH * NE + BATCH * TOPK + bb * TOPK + rank] = score;     // values
        }

        // p = 1 - norm_cdf((thr - logit)/noise_std)
        s_p[idx]     = 0.5f * erfcf((thr - logit) * (float)NE * 0.70710678118654752f);
        s_clean[idx] = clean;
    }
    __syncthreads();

    // aux loss: fold 64 rows -> 16 rows -> ... -> 1 row (parallel tree)
    s_clean[tid] += s_clean[tid + 256] + s_clean[tid + 512] + s_clean[tid + 768];
    s_p[tid]     += s_p[tid + 256]     + s_p[tid + 512]     + s_p[tid + 768];
    __syncthreads();
#pragma unroll
    for (int st = 128; st >= 16; st >>= 1) {
        if (tid < st) {
            s_clean[tid] += s_clean[tid + st];
            s_p[tid]     += s_p[tid + st];
        }
        __syncthreads();
    }

    if (tid < 32) {
        float imp = 0.0f, pm = 0.0f;
        if (tid < 16) {
            imp = s_clean[tid] * complexity[tid];
            pm  = s_p[tid] * (1.0f / (float)BATCH);
        }
        float im = imp, pmn = pm;
#pragma unroll
        for (int m = 8; m; m >>= 1) {
            im  += __shfl_xor_sync(0xffffffffu, im,  m);
            pmn += __shfl_xor_sync(0xffffffffu, pmn, m);
        }
        im  *= (1.0f / (float)NE);
        pmn *= (1.0f / (float)NE);
        float dv = (tid < 16) ? (imp - im)  * (imp - im)  : 0.0f;
        float dp = (tid < 16) ? (pm  - pmn) * (pm  - pmn) : 0.0f;
#pragma unroll
        for (int m = 8; m; m >>= 1) {
            dv += __shfl_xor_sync(0xffffffffu, dv, m);
            dp += __shfl_xor_sync(0xffffffffu, dp, m);
        }
        if (tid == 0) {
            float imp_loss  = (dv / (float)(NE - 1)) / ((im  + 1e-8f) * (im  + 1e-8f));
            float load_loss = (dp / (float)(NE - 1)) / ((pmn + 1e-8f) * (pmn + 1e-8f));
            out[BATCH * NE + 2 * BATCH * TOPK] = 0.5f * imp_loss + 0.5f * load_loss;
            g_counter = 0u;                  // restore for next replay
        }
    }
}

// ---------------------------------------------------------------------------
extern "C" void kernel_launch(void* const* d_in, const int* in_sizes, int n_in,
                              void* d_out, int out_size) {
    const float* x          = (const float*)d_in[0];
    const float* freq_emb   = (const float*)d_in[1];
    const float* gate_w     = (const float*)d_in[2];
    const float* fgate_w    = (const float*)d_in[3];
    const float* complexity = (const float*)d_in[4];
    const float* noise      = (const float*)d_in[5];
    float* out = (float*)d_out;

    routing_fused_kernel<<<NBLOCKS, 256>>>(x, gate_w, freq_emb, fgate_w,
                                           noise, complexity, out);
}